// round 6
// baseline (speedup 1.0000x reference)
#include <cuda_runtime.h>
#include <math.h>
#include <stdint.h>

#define NN 10000
#define EE 160000
#define OUTC 12

typedef unsigned long long u64;

// ---------------- scratch (device globals; no allocation allowed) ----------------
__device__ float g_bufA[NN * 64 * 12];
__device__ float g_bufB[NN * 64 * 12];
__device__ int   g_cnt[NN];
__device__ int   g_fill[NN];
__device__ int   g_rowptr[NN + 1];
__device__ int   g_col[EE + NN];
__device__ float g_deg[NN];
__device__ float g_dis[NN];
__device__ float g_wc[EE + NN];
// prepacked conv weights: [(k*cin+ci)*64 + ch] = (w[ch][ci][k], w[ch+64][ci][k])
__device__ float2 g_wp1[3 * 32 * 64];
__device__ float2 g_wp2[3 * 64 * 64];
__device__ float2 g_wp3[3 * 64 * 64];
__device__ float2 g_wp4[3 * 64 * 64];
__device__ float2 g_bp1[64], g_bp2[64], g_bp3[64], g_bp4[64];

// ---------------- f32x2 helpers ----------------
__device__ __forceinline__ u64 pk2(float a, float b) {
    u64 r; asm("mov.b64 %0, {%1, %2};" : "=l"(r) : "f"(a), "f"(b)); return r;
}
__device__ __forceinline__ void upk2(u64 v, float& a, float& b) {
    asm("mov.b64 {%0, %1}, %2;" : "=f"(a), "=f"(b) : "l"(v));
}
__device__ __forceinline__ u64 ffma2(u64 a, u64 b, u64 c) {
    u64 d; asm("fma.rn.f32x2 %0, %1, %2, %3;" : "=l"(d) : "l"(a), "l"(b), "l"(c)); return d;
}

// ---------------- CSR build (proven) ----------------
__global__ void csr_init(int* cnt, float* deg, int* fill) {
    int v = blockIdx.x * blockDim.x + threadIdx.x;
    if (v < NN) { cnt[v] = 1; deg[v] = 1.0f; fill[v] = 0; }
}
__global__ void csr_count(const int* __restrict__ dst, const float* __restrict__ ew,
                          int* cnt, float* deg) {
    int e = blockIdx.x * blockDim.x + threadIdx.x;
    if (e < EE) {
        int d = dst[e];
        atomicAdd(&cnt[d], 1);
        atomicAdd(&deg[d], ew[e]);
    }
}
__global__ void csr_dis(const float* __restrict__ deg, float* dis) {
    int v = blockIdx.x * blockDim.x + threadIdx.x;
    if (v < NN) dis[v] = rsqrtf(deg[v]);
}
__global__ void scan_kernel(const int* __restrict__ cnt, int* __restrict__ rowptr) {
    __shared__ int part[1024];
    const int tid = threadIdx.x;
    const int CHUNK = 10;
    int base = tid * CHUNK;
    int local[CHUNK];
    int s = 0;
#pragma unroll
    for (int i = 0; i < CHUNK; i++) {
        int idx = base + i;
        int v = (idx < NN) ? cnt[idx] : 0;
        local[i] = s;
        s += v;
    }
    part[tid] = s;
    __syncthreads();
    for (int off = 1; off < 1024; off <<= 1) {
        int v = (tid >= off) ? part[tid - off] : 0;
        __syncthreads();
        part[tid] += v;
        __syncthreads();
    }
    int offset = (tid > 0) ? part[tid - 1] : 0;
#pragma unroll
    for (int i = 0; i < CHUNK; i++) {
        int idx = base + i;
        if (idx <= NN) rowptr[idx] = offset + local[i];
    }
}
__global__ void csr_fill(const int* __restrict__ src, const int* __restrict__ dst,
                         const float* __restrict__ ew, const float* __restrict__ dis,
                         const int* __restrict__ rowptr, int* fill,
                         int* __restrict__ col, float* __restrict__ wc) {
    int i = blockIdx.x * blockDim.x + threadIdx.x;
    if (i < EE) {
        int s = src[i], d = dst[i];
        int pos = rowptr[d] + atomicAdd(&fill[d], 1);
        col[pos] = s;
        wc[pos] = dis[s] * ew[i] * dis[d];
    } else if (i < EE + NN) {
        int v = i - EE;
        int pos = rowptr[v] + atomicAdd(&fill[v], 1);
        col[pos] = v;
        wc[pos] = dis[v] * dis[v];
    }
}

// ---------------- conv weight prepack: (wP, wQ) pairs, [k][ci][ch] ----------------
__global__ void prepack(const float* __restrict__ w, const float* __restrict__ b,
                        float2* __restrict__ wp, float2* __restrict__ bp, int cin) {
    int i = blockIdx.x * blockDim.x + threadIdx.x;
    int total = 3 * cin * 64;
    if (i < total) {
        int ch = i & 63;
        int kc = i >> 6;            // k*cin + ci
        int k = kc / cin, ci = kc - k * cin;
        wp[i] = make_float2(w[ch * cin * 3 + ci * 3 + k],
                            w[(ch + 64) * cin * 3 + ci * 3 + k]);
    }
    if (i < 64) bp[i] = make_float2(b[i], b[i + 64]);
}

// ---------------- gated temporal conv, restructured ----------------
// Tile = 8 nodes. Shared: Xdup [CIN][118] u64 (value duplicated (x,x)); node nl occupies
// slots 14*nl .. 14*nl+13, with slot 0 and 13 zero (conv padding), data at 1..12.
// Ws [3*CIN*64] u64 of (wP,wQ) pairs. Thread (256): warp = node, lane = chgrp(4ch)*2+half.
// acc[cp][j] = (P_{ch}[t0+j], Q_{ch}[t0+j]) as f32x2; 72 FFMA2 per ci.
template <int CIN>
__global__ void __launch_bounds__(256, 1) conv_simt(
        const float2* __restrict__ Wp, const float2* __restrict__ Bp,
        const float* __restrict__ xin,   // [node][CIN][12]
        float* __restrict__ xout)        // [node][64][12]
{
    extern __shared__ char sm[];
    u64* Xs = (u64*)sm;                          // [CIN][118]
    u64* Ws = (u64*)(sm + CIN * 118 * 8);        // [3*CIN*64]

    const int tid = threadIdx.x;
    const int node_l = tid >> 5;                 // 0..7
    const int lane = tid & 31;
    const int chgrp = lane >> 1;                 // 0..15
    const int half = lane & 1;
    const int t0 = half * 6;

    // W -> shared (once per CTA)
    for (int i = tid; i < 3 * CIN * 64; i += 256) {
        float2 w = Wp[i];
        Ws[i] = pk2(w.x, w.y);
    }
    u64 bias[4];
#pragma unroll
    for (int cp = 0; cp < 4; cp++) {
        float2 b = Bp[chgrp * 4 + cp];
        bias[cp] = pk2(b.x, b.y);
    }

    for (int grp = blockIdx.x; grp < NN / 8; grp += gridDim.x) {
        // ---- fill X tile (duplicated) ----
        for (int p = tid; p < 8 * CIN; p += 256) {
            int nl = p / CIN, ci = p - nl * CIN;
            const float4* srcp = (const float4*)(xin + ((size_t)(grp * 8 + nl) * CIN + ci) * 12);
            float4 a = srcp[0], b4 = srcp[1], c4 = srcp[2];
            u64* row = Xs + ci * 118 + nl * 14;
            row[0] = 0; row[13] = 0;
            row[1]  = pk2(a.x, a.x);  row[2]  = pk2(a.y, a.y);
            row[3]  = pk2(a.z, a.z);  row[4]  = pk2(a.w, a.w);
            row[5]  = pk2(b4.x, b4.x); row[6]  = pk2(b4.y, b4.y);
            row[7]  = pk2(b4.z, b4.z); row[8]  = pk2(b4.w, b4.w);
            row[9]  = pk2(c4.x, c4.x); row[10] = pk2(c4.y, c4.y);
            row[11] = pk2(c4.z, c4.z); row[12] = pk2(c4.w, c4.w);
        }
        __syncthreads();

        // ---- main FMA loop ----
        u64 acc[4][6];
#pragma unroll
        for (int cp = 0; cp < 4; cp++)
#pragma unroll
            for (int j = 0; j < 6; j++) acc[cp][j] = bias[cp];

        const u64* xbase = Xs + node_l * 14 + t0;     // + ci*118
        const u64* wbase = Ws + chgrp * 4;            // + (k*CIN+ci)*64

#pragma unroll 2
        for (int ci = 0; ci < CIN; ci++) {
            u64 xd[8];
            const ulonglong2* xp = (const ulonglong2*)(xbase + ci * 118);
#pragma unroll
            for (int q = 0; q < 4; q++) {
                ulonglong2 v = xp[q];
                xd[2 * q] = v.x; xd[2 * q + 1] = v.y;
            }
#pragma unroll
            for (int k = 0; k < 3; k++) {
                const ulonglong2* wpp = (const ulonglong2*)(wbase + (k * CIN + ci) * 64);
                ulonglong2 w01 = wpp[0], w23 = wpp[1];
                u64 wv[4] = { w01.x, w01.y, w23.x, w23.y };
#pragma unroll
                for (int cp = 0; cp < 4; cp++)
#pragma unroll
                    for (int j = 0; j < 6; j++)
                        acc[cp][j] = ffma2(wv[cp], xd[j + k], acc[cp][j]);
            }
        }

        // ---- epilogue: gate + store ----
        const int gnode = grp * 8 + node_l;
#pragma unroll
        for (int cp = 0; cp < 4; cp++) {
            int ch = chgrp * 4 + cp;
            float2* orow = (float2*)(xout + ((size_t)gnode * 64 + ch) * 12 + t0);
#pragma unroll
            for (int jp = 0; jp < 3; jp++) {
                float p0, q0, p1, q1;
                upk2(acc[cp][2 * jp], p0, q0);
                upk2(acc[cp][2 * jp + 1], p1, q1);
                float2 o;
                o.x = p0 / (1.0f + __expf(-q0));
                o.y = p1 / (1.0f + __expf(-q1));
                orow[jp] = o;
            }
        }
        __syncthreads();   // Xs reusable next group
    }
}

// ---------------- GCN aggregation (proven, 768-stride) ----------------
__global__ void __launch_bounds__(256) agg_kernel(
        const float* __restrict__ hin, const int* __restrict__ rowptr,
        const int* __restrict__ col, const float* __restrict__ wc,
        float* __restrict__ out)
{
    const int v = blockIdx.x;
    const int tid = threadIdx.x;
    const int beg = rowptr[v], end = rowptr[v + 1];
    float a0 = 0.f, a1 = 0.f, a2 = 0.f;
    __shared__ int scol[64];
    __shared__ float sw[64];
    for (int j0 = beg; j0 < end; j0 += 64) {
        int m = min(64, end - j0);
        if (tid < m) { scol[tid] = col[j0 + tid] * 768; sw[tid] = wc[j0 + tid]; }
        __syncthreads();
#pragma unroll 4
        for (int i = 0; i < m; i++) {
            const float* p = hin + scol[i];
            float w = sw[i];
            a0 = fmaf(w, p[tid], a0);
            a1 = fmaf(w, p[tid + 256], a1);
            a2 = fmaf(w, p[tid + 512], a2);
        }
        __syncthreads();
    }
    float* o = out + (size_t)v * 768;
    o[tid] = a0; o[tid + 256] = a1; o[tid + 512] = a2;
}

// ---------------- GCN transform (proven): out = relu(W @ agg + b) ----------------
__global__ void __launch_bounds__(256) gcn_transform(
        const float* __restrict__ agg, const float* __restrict__ W,
        const float* __restrict__ b, float* __restrict__ out)
{
    const int o = threadIdx.x;
    const int ln = threadIdx.y;
    const int node = blockIdx.x * 4 + ln;
    __shared__ u64 xs[4][64][6];
    __shared__ float Wsh[64][65];

    const float2* ar = (const float2*)(agg + (size_t)node * 768 + o * 12);
#pragma unroll
    for (int j = 0; j < 6; j++) { float2 v = ar[j]; xs[ln][o][j] = pk2(v.x, v.y); }
    for (int i = ln * 64 + o; i < 4096; i += 256) {
        int orow = i >> 6, c = i & 63;
        Wsh[c][orow] = W[i];
    }
    __syncthreads();

    u64 acc[6];
    {
        float bo = b[o];
        u64 b0 = pk2(bo, bo);
#pragma unroll
        for (int j = 0; j < 6; j++) acc[j] = b0;
    }
#pragma unroll 4
    for (int c = 0; c < 64; c++) {
        float w = Wsh[c][o];
        u64 wp = pk2(w, w);
#pragma unroll
        for (int j = 0; j < 6; j++) acc[j] = ffma2(wp, xs[ln][c][j], acc[j]);
    }

    float ov[12];
#pragma unroll
    for (int j = 0; j < 6; j++) {
        float p, q; upk2(acc[j], p, q);
        ov[2 * j]     = fmaxf(p, 0.0f);
        ov[2 * j + 1] = fmaxf(q, 0.0f);
    }
    float4* orow = (float4*)(out + (size_t)node * 768 + o * 12);
#pragma unroll
    for (int j = 0; j < 3; j++)
        orow[j] = make_float4(ov[4 * j], ov[4 * j + 1], ov[4 * j + 2], ov[4 * j + 3]);
}

// ---------------- final conv: warp per node, fw in shared ----------------
__global__ void __launch_bounds__(256) final_conv(
        const float* __restrict__ h, const float* __restrict__ fw,
        const float* __restrict__ fb, float* __restrict__ out)
{
    __shared__ float fws[12 * 768];
    __shared__ float fbs[12];
    const int tid = threadIdx.x;
    for (int i = tid; i < 12 * 768; i += 256) fws[i] = fw[i];
    if (tid < 12) fbs[tid] = fb[tid];
    __syncthreads();

    const int wid = tid >> 5, lane = tid & 31;
    const int node = blockIdx.x * 8 + wid;

    const float4* hr = (const float4*)(h + (size_t)node * 768) + lane * 6;
    float4 hv[6];
#pragma unroll
    for (int q = 0; q < 6; q++) hv[q] = hr[q];

#pragma unroll 1
    for (int o = 0; o < 12; o++) {
        const float4* wr = (const float4*)(fws + o * 768) + lane * 6;
        float acc = 0.f;
#pragma unroll
        for (int q = 0; q < 6; q++) {
            float4 wv = wr[q];
            acc += hv[q].x * wv.x + hv[q].y * wv.y + hv[q].z * wv.z + hv[q].w * wv.w;
        }
#pragma unroll
        for (int m = 16; m; m >>= 1) acc += __shfl_xor_sync(0xffffffffu, acc, m);
        if (lane == o) out[node * 12 + o] = acc + fbs[o];
    }
}

// ---------------- launch ----------------
extern "C" void kernel_launch(void* const* d_in, const int* in_sizes, int n_in,
                              void* d_out, int out_size) {
    const float* x      = (const float*)d_in[0];
    const int*   ei     = (const int*)d_in[1];
    const float* ew     = (const float*)d_in[2];
    const float* tc1a_w = (const float*)d_in[3];
    const float* tc1a_b = (const float*)d_in[4];
    const float* gc1_w  = (const float*)d_in[5];
    const float* gc1_b  = (const float*)d_in[6];
    const float* tc1b_w = (const float*)d_in[7];
    const float* tc1b_b = (const float*)d_in[8];
    const float* tc2a_w = (const float*)d_in[9];
    const float* tc2a_b = (const float*)d_in[10];
    const float* gc2_w  = (const float*)d_in[11];
    const float* gc2_b  = (const float*)d_in[12];
    const float* tc2b_w = (const float*)d_in[13];
    const float* tc2b_b = (const float*)d_in[14];
    const float* fin_w  = (const float*)d_in[15];
    const float* fin_b  = (const float*)d_in[16];

    const int* src = ei;
    const int* dst = ei + EE;

    float *bufA, *bufB, *deg, *dis, *wc;
    int *cnt, *fill, *rowptr, *col;
    float2 *wp1, *wp2, *wp3, *wp4, *bp1, *bp2, *bp3, *bp4;
    cudaGetSymbolAddress((void**)&bufA,   g_bufA);
    cudaGetSymbolAddress((void**)&bufB,   g_bufB);
    cudaGetSymbolAddress((void**)&deg,    g_deg);
    cudaGetSymbolAddress((void**)&dis,    g_dis);
    cudaGetSymbolAddress((void**)&wc,     g_wc);
    cudaGetSymbolAddress((void**)&cnt,    g_cnt);
    cudaGetSymbolAddress((void**)&fill,   g_fill);
    cudaGetSymbolAddress((void**)&rowptr, g_rowptr);
    cudaGetSymbolAddress((void**)&col,    g_col);
    cudaGetSymbolAddress((void**)&wp1,    g_wp1);
    cudaGetSymbolAddress((void**)&wp2,    g_wp2);
    cudaGetSymbolAddress((void**)&wp3,    g_wp3);
    cudaGetSymbolAddress((void**)&wp4,    g_wp4);
    cudaGetSymbolAddress((void**)&bp1,    g_bp1);
    cudaGetSymbolAddress((void**)&bp2,    g_bp2);
    cudaGetSymbolAddress((void**)&bp3,    g_bp3);
    cudaGetSymbolAddress((void**)&bp4,    g_bp4);

    const int SMEM32 = 32 * 118 * 8 + 3 * 32 * 64 * 8;   // 79360
    const int SMEM64 = 64 * 118 * 8 + 3 * 64 * 64 * 8;   // 158720
    cudaFuncSetAttribute(conv_simt<32>, cudaFuncAttributeMaxDynamicSharedMemorySize, SMEM32);
    cudaFuncSetAttribute(conv_simt<64>, cudaFuncAttributeMaxDynamicSharedMemorySize, SMEM64);

    // CSR build
    csr_init<<<(NN + 255) / 256, 256>>>(cnt, deg, fill);
    csr_count<<<(EE + 255) / 256, 256>>>(dst, ew, cnt, deg);
    csr_dis<<<(NN + 255) / 256, 256>>>(deg, dis);
    scan_kernel<<<1, 1024>>>(cnt, rowptr);
    csr_fill<<<(EE + NN + 255) / 256, 256>>>(src, dst, ew, dis, rowptr, fill, col, wc);

    // weight prepack
    prepack<<<(3 * 32 * 64 + 255) / 256, 256>>>(tc1a_w, tc1a_b, wp1, bp1, 32);
    prepack<<<(3 * 64 * 64 + 255) / 256, 256>>>(tc1b_w, tc1b_b, wp2, bp2, 64);
    prepack<<<(3 * 64 * 64 + 255) / 256, 256>>>(tc2a_w, tc2a_b, wp3, bp3, 64);
    prepack<<<(3 * 64 * 64 + 255) / 256, 256>>>(tc2b_w, tc2b_b, wp4, bp4, 64);

    dim3 tb(64, 4);
    // block 1
    conv_simt<32><<<148, 256, SMEM32>>>(wp1, bp1, x, bufA);
    agg_kernel<<<NN, 256>>>(bufA, rowptr, col, wc, bufB);
    gcn_transform<<<NN / 4, tb>>>(bufB, gc1_w, gc1_b, bufA);
    conv_simt<64><<<148, 256, SMEM64>>>(wp2, bp2, bufA, bufB);
    // block 2
    conv_simt<64><<<148, 256, SMEM64>>>(wp3, bp3, bufB, bufA);
    agg_kernel<<<NN, 256>>>(bufA, rowptr, col, wc, bufB);
    gcn_transform<<<NN / 4, tb>>>(bufB, gc2_w, gc2_b, bufA);
    conv_simt<64><<<148, 256, SMEM64>>>(wp4, bp4, bufA, bufB);
    // head
    final_conv<<<NN / 8, 256>>>(bufB, fin_w, fin_b, (float*)d_out);
}